// round 3
// baseline (speedup 1.0000x reference)
#include <cuda_runtime.h>
#include <math_constants.h>

// Problem constants (fixed by the reference: B=8, N=4096, D=2)
#define BQ      8
#define NPTS    4096
#define THREADS 256
#define IPT     2                   // query points per thread
#define TILE    (THREADS * IPT)     // 512 queries per block
#define NTILES  (NPTS / TILE)       // 8
#define NBLOCKS (NTILES * BQ * 2)   // 128
#define CHUNK   2048                // reference points staged per shared pass
#define NCHUNK  (NPTS / CHUNK)      // 2

__device__ float g_partials[NBLOCKS];

// One block: (tile of 512 query points) x (batch) x (direction).
// dir 0: queries = y_true, reference set = y_pred  (also fuses EMD terms)
// dir 1: queries = y_pred, reference set = y_true
__global__ __launch_bounds__(THREADS, 1)
void chamfer_kernel(const float* __restrict__ yt, const float* __restrict__ yp) {
    __shared__ float4 spts[CHUNK];    // (px, py, px^2+py^2, pad) : 32 KB
    __shared__ float  red[THREADS];   // block reduction           : 1 KB

    const int b   = blockIdx.y;
    const int dir = blockIdx.z;
    const float* srcBase = (dir == 0 ? yt : yp) + (size_t)b * NPTS * 2; // queries
    const float* refBase = (dir == 0 ? yp : yt) + (size_t)b * NPTS * 2; // reference set

    const int i0 = blockIdx.x * TILE + threadIdx.x;

    float ax[IPT], ay[IPT], xx[IPT], best[IPT];
#pragma unroll
    for (int k = 0; k < IPT; k++) {
        const float2 q = reinterpret_cast<const float2*>(srcBase)[i0 + k * THREADS];
        ax[k]   = -2.0f * q.x;
        ay[k]   = -2.0f * q.y;
        xx[k]   = fmaf(q.x, q.x, q.y * q.y);
        best[k] = CUDART_INF_F;
    }

    for (int c = 0; c < NCHUNK; c++) {
        __syncthreads();
        // cooperative stage of 2048 reference points, pp precomputed
        for (int j = threadIdx.x; j < CHUNK; j += THREADS) {
            const float2 p = reinterpret_cast<const float2*>(refBase)[c * CHUNK + j];
            spts[j] = make_float4(p.x, p.y, fmaf(p.x, p.x, p.y * p.y), 0.0f);
        }
        __syncthreads();

#pragma unroll 4
        for (int j = 0; j < CHUNK; j++) {
            const float4 p = spts[j];   // LDS.128, broadcast (conflict-free)
#pragma unroll
            for (int k = 0; k < IPT; k++) {
                float t = fmaf(ax[k], p.x, p.z);   // pp - 2*x*px
                t = fmaf(ay[k], p.y, t);           //    - 2*y*py
                best[k] = fminf(best[k], t);       // alu pipe, overlaps fma
            }
        }
    }

    // NN squared distance: max(xx + best, 0); clamp commutes with min.
    float local = 0.0f;
#pragma unroll
    for (int k = 0; k < IPT; k++)
        local += fmaxf(xx[k] + best[k], 0.0f);
    local *= (1.0f / BQ);   // mean over batch of per-batch sums

    if (dir == 0) {
        // Fused EMD approximation: cumsum over D=2 -> (t0-p0)^2 + (t0+t1-p0-p1)^2
        const float* tb = yt + (size_t)b * NPTS * 2;
        const float* pb = yp + (size_t)b * NPTS * 2;
        float e = 0.0f;
#pragma unroll
        for (int k = 0; k < IPT; k++) {
            const int i = i0 + k * THREADS;
            const float2 t = reinterpret_cast<const float2*>(tb)[i];
            const float2 p = reinterpret_cast<const float2*>(pb)[i];
            const float d0 = t.x - p.x;
            const float d1 = (t.x + t.y) - (p.x + p.y);
            e = fmaf(d0, d0, e);
            e = fmaf(d1, d1, e);
        }
        local += e * (1.0f / ((float)BQ * NPTS * 2));
    }

    // Deterministic block tree reduction
    red[threadIdx.x] = local;
    __syncthreads();
    for (int s = THREADS / 2; s > 0; s >>= 1) {
        if (threadIdx.x < s) red[threadIdx.x] += red[threadIdx.x + s];
        __syncthreads();
    }
    if (threadIdx.x == 0) {
        const int bid = (blockIdx.z * gridDim.y + blockIdx.y) * gridDim.x + blockIdx.x;
        g_partials[bid] = red[0];
    }
}

// Deterministic fixed-order final sum of the 128 block partials.
__global__ void finalize_kernel(float* __restrict__ out) {
    if (threadIdx.x == 0 && blockIdx.x == 0) {
        float s = 0.0f;
        for (int i = 0; i < NBLOCKS; i++) s += g_partials[i];
        out[0] = s;
    }
}

extern "C" void kernel_launch(void* const* d_in, const int* in_sizes, int n_in,
                              void* d_out, int out_size) {
    const float* y_true = (const float*)d_in[0];
    const float* y_pred = (const float*)d_in[1];
    float* out = (float*)d_out;

    dim3 grid(NTILES, BQ, 2);
    chamfer_kernel<<<grid, THREADS>>>(y_true, y_pred);
    finalize_kernel<<<1, 32>>>(out);
}